// round 9
// baseline (speedup 1.0000x reference)
#include <cuda_runtime.h>

#define BB 256
#define TT 512
#define KK 128

// ---- scratch (no allocations allowed) ----
__device__ unsigned char g_bp[(long)BB * TT * KK];   // 16MB backpointers
__device__ float g_vfin[BB * KK];                    // final viterbi row per batch
__device__ int   g_order[BB];                        // batches sorted by length desc
__device__ float g_lognorm[BB];
__device__ float g_ll[BB];
__device__ int   g_correct[BB];
__device__ int   g_total[BB];

// ---- packed f32x2 helpers (sm_103a): add/fma only (no packed max!) ----
__device__ __forceinline__ unsigned long long f2pack(float a, float b) {
    unsigned long long r;
    asm("mov.b64 %0, {%1,%2};" : "=l"(r) : "f"(a), "f"(b));
    return r;
}
__device__ __forceinline__ void f2unpack(unsigned long long v, float& a, float& b) {
    asm("mov.b64 {%0,%1}, %2;" : "=f"(a), "=f"(b) : "l"(v));
}
__device__ __forceinline__ unsigned long long f2fma(unsigned long long a, unsigned long long b,
                                                    unsigned long long c) {
    unsigned long long r;
    asm("fma.rn.f32x2 %0, %1, %2, %3;" : "=l"(r) : "l"(a), "l"(b), "l"(c));
    return r;
}

// ============================================================
// Kernel 0: rank-sort batches by length descending (LPT).
// ============================================================
__global__ void sort_kernel(const int* __restrict__ lengths)
{
    __shared__ int keys[BB];
    int b = threadIdx.x;
    int key = (lengths[b] << 8) | (BB - 1 - b);
    keys[b] = key;
    __syncthreads();
    int r = 0;
    #pragma unroll 8
    for (int j = 0; j < BB; j++) r += (keys[j] > key);
    g_order[r] = b;
}

// ============================================================
// Kernel 1: fused scans with early exit at t = len.
// Blocks [0,256) = Viterbi forward WITH backpointer tracking,
// blocks [256,512) = CRF forward (exp-domain logsumexp).
// One thread per destination tag k.
// ============================================================
__global__ __launch_bounds__(128)
void crf_scan_kernel(const float* __restrict__ emissions,
                     const int*   __restrict__ lengths,
                     const float* __restrict__ trans)
{
    __shared__ float4 bufS[2][KK / 4];   // state vector (double buffer)
    __shared__ float  redS[2][4];

    const int k    = threadIdx.x;
    const int role = (blockIdx.x >= BB);
    const int b    = g_order[role ? (blockIdx.x - BB) : blockIdx.x];
    const int len  = lengths[b];
    const float* em = emissions + (long)b * TT * KK;
    const int wid = k >> 5, lane = k & 31;

    if (!role) {
        // -------- Viterbi forward with argmax tracking, t < len --------
        float tr[KK];                         // transition column k in registers
        #pragma unroll
        for (int j = 0; j < KK; j++) tr[j] = trans[j * KK + k];

        unsigned char* bp = g_bp + (long)b * TT * KK;

        float v = em[k];                      // t = 0
        int buf = 0;
        ((float*)bufS[0])[k] = v;
        __syncthreads();

        float emit = em[KK + k];              // prefetch t = 1
        for (int t = 1; t < len; t++) {
            float emit_next = (t + 1 < TT) ? em[(t + 1) * KK + k] : 0.0f;

            // 4 independent (value,index) chains; strict > keeps first index
            float4 q0 = bufS[buf][0];
            float b0 = q0.x + tr[0]; int i0 = 0;
            float b1 = q0.y + tr[1]; int i1 = 1;
            float b2 = q0.z + tr[2]; int i2 = 2;
            float b3 = q0.w + tr[3]; int i3 = 3;
            #pragma unroll
            for (int jj = 1; jj < KK / 4; jj++) {
                float4 q = bufS[buf][jj];
                float w0 = q.x + tr[4*jj + 0];
                float w1 = q.y + tr[4*jj + 1];
                float w2 = q.z + tr[4*jj + 2];
                float w3 = q.w + tr[4*jj + 3];
                if (w0 > b0) { b0 = w0; i0 = 4*jj + 0; }
                if (w1 > b1) { b1 = w1; i1 = 4*jj + 1; }
                if (w2 > b2) { b2 = w2; i2 = 4*jj + 2; }
                if (w3 > b3) { b3 = w3; i3 = 4*jj + 3; }
            }
            // combine with exact first-index tie-break
            float best = b0; int bi = i0;
            if (b1 > best || (b1 == best && i1 < bi)) { best = b1; bi = i1; }
            if (b2 > best || (b2 == best && i2 < bi)) { best = b2; bi = i2; }
            if (b3 > best || (b3 == best && i3 < bi)) { best = b3; bi = i3; }

            v = best + emit;
            bp[t * KK + k] = (unsigned char)bi;

            ((float*)bufS[buf ^ 1])[k] = v;
            __syncthreads();
            buf ^= 1;
            emit = emit_next;
        }
        g_vfin[b * KK + k] = v;
    } else {
        // -------- CRF forward (log partition), exp-domain, t < len --------
        unsigned long long Ep[KK / 2];       // packed exp(transition) column k
        #pragma unroll
        for (int m = 0; m < KK / 2; m++)
            Ep[m] = f2pack(__expf(trans[(2 * m) * KK + k]),
                           __expf(trans[(2 * m + 1) * KK + k]));

        float alpha = em[k];
        int buf = 1;                         // first write goes to nb = 0

        float emit = em[KK + k];
        for (int t = 1; t < len; t++) {
            float emit_next = (t + 1 < TT) ? em[(t + 1) * KK + k] : 0.0f;

            // per-warp max of alpha
            float mw = alpha;
            #pragma unroll
            for (int o = 16; o > 0; o >>= 1)
                mw = fmaxf(mw, __shfl_xor_sync(0xffffffffu, mw, o));

            int nb = buf ^ 1;
            float p = __expf(alpha - mw);
            ((float*)bufS[nb])[k] = p;
            if (lane == 0) redS[nb][wid] = mw;
            __syncthreads();

            float m0 = redS[nb][0], m1 = redS[nb][1];
            float m2 = redS[nb][2], m3 = redS[nb][3];
            float m = fmaxf(fmaxf(m0, m1), fmaxf(m2, m3));

            // grouped packed dot: group g = warp g's p's (rescaled after)
            const ulonglong2* bp2 = (const ulonglong2*)bufS[nb];
            unsigned long long acc0 = f2pack(0.f, 0.f), acc1 = acc0,
                               acc2 = acc0, acc3 = acc0;
            #pragma unroll
            for (int jj = 0; jj < 8; jj++) {
                ulonglong2 q = bp2[jj];
                acc0 = f2fma(q.x, Ep[2 * jj],     acc0);
                acc0 = f2fma(q.y, Ep[2 * jj + 1], acc0);
            }
            #pragma unroll
            for (int jj = 8; jj < 16; jj++) {
                ulonglong2 q = bp2[jj];
                acc1 = f2fma(q.x, Ep[2 * jj],     acc1);
                acc1 = f2fma(q.y, Ep[2 * jj + 1], acc1);
            }
            #pragma unroll
            for (int jj = 16; jj < 24; jj++) {
                ulonglong2 q = bp2[jj];
                acc2 = f2fma(q.x, Ep[2 * jj],     acc2);
                acc2 = f2fma(q.y, Ep[2 * jj + 1], acc2);
            }
            #pragma unroll
            for (int jj = 24; jj < 32; jj++) {
                ulonglong2 q = bp2[jj];
                acc3 = f2fma(q.x, Ep[2 * jj],     acc3);
                acc3 = f2fma(q.y, Ep[2 * jj + 1], acc3);
            }
            float lo, hi, s;
            f2unpack(acc0, lo, hi); s = __expf(m0 - m) * (lo + hi);
            f2unpack(acc1, lo, hi); s = fmaf(__expf(m1 - m), lo + hi, s);
            f2unpack(acc2, lo, hi); s = fmaf(__expf(m2 - m), lo + hi, s);
            f2unpack(acc3, lo, hi); s = fmaf(__expf(m3 - m), lo + hi, s);

            alpha = m + __logf(s) + emit;
            buf = nb;
            emit = emit_next;
        }

        // final logsumexp over k
        __syncthreads();
        float mw = alpha;
        #pragma unroll
        for (int o = 16; o > 0; o >>= 1)
            mw = fmaxf(mw, __shfl_xor_sync(0xffffffffu, mw, o));
        if (lane == 0) redS[0][wid] = mw;
        __syncthreads();
        float m = fmaxf(fmaxf(redS[0][0], redS[0][1]), fmaxf(redS[0][2], redS[0][3]));
        float p = __expf(alpha - m);
        #pragma unroll
        for (int o = 16; o > 0; o >>= 1)
            p += __shfl_xor_sync(0xffffffffu, p, o);
        __syncthreads();
        if (lane == 0) redS[0][wid] = p;
        __syncthreads();
        if (k == 0) {
            float s = redS[0][0] + redS[0][1] + redS[0][2] + redS[0][3];
            g_lognorm[b] = m + __logf(s);
        }
    }
}

// ============================================================
// Kernel 2: backtrack via stored backpointers, chunked
// double-buffered smem staging. Thread 0 chases pointers in
// smem (LDS ~29cyc/step); threads 1..127 stage the next chunk.
// Also computes gold score + accuracy + decoded output.
// ============================================================
__global__ __launch_bounds__(128)
void crf_backtrack_kernel(const float* __restrict__ emissions,
                          const int*   __restrict__ tag_ids,
                          const int*   __restrict__ lengths,
                          const float* __restrict__ trans,
                          float*       __restrict__ out)
{
    __shared__ unsigned char bpS[2][64 * KK];   // 16KB double buffer
    __shared__ int   tagS[TT];
    __shared__ float fredS[4];
    __shared__ int   iredS[4];
    __shared__ int   curS;

    const int b = blockIdx.x, k = threadIdx.x;
    const int wid = k >> 5, lane = k & 31;
    const int len = lengths[b];
    const int t0  = len - 1;

    // ---- last_tag = argmax(g_vfin row), first index on ties ----
    float v = g_vfin[b * KK + k];
    int idx = k;
    #pragma unroll
    for (int o = 16; o > 0; o >>= 1) {
        float ov = __shfl_xor_sync(0xffffffffu, v, o);
        int   oi = __shfl_xor_sync(0xffffffffu, idx, o);
        if (ov > v || (ov == v && oi < idx)) { v = ov; idx = oi; }
    }
    if (lane == 0) { fredS[wid] = v; iredS[wid] = idx; }
    __syncthreads();
    if (k == 0) {
        float bv = fredS[0]; int bi = iredS[0];
        #pragma unroll
        for (int w = 1; w < 4; w++)
            if (fredS[w] > bv || (fredS[w] == bv && iredS[w] < bi)) {
                bv = fredS[w]; bi = iredS[w];
            }
        curS = bi;
    }
    __syncthreads();
    int cur = curS;

    // fill tail [t0, TT) with last_tag (matches identity backpointers)
    for (int t = t0 + k; t < TT; t += 128) tagS[t] = cur;

    // ---- chunked walk: chunk c covers rows [c*64, c*64+64) ----
    const int ctop = (t0 >= 1) ? (t0 >> 6) : 0;
    {   // stage top chunk into buffer 0
        const uint4* src = (const uint4*)(g_bp + ((long)b * TT + ctop * 64) * KK);
        uint4* dst = (uint4*)bpS[0];
        for (int i = k; i < 64 * KK / 16; i += 128) dst[i] = src[i];
    }
    __syncthreads();

    for (int c = ctop; c >= 0; c--) {
        int p = (ctop - c) & 1;
        if (k == 0) {
            int base = c * 64;
            int hi = (t0 < base + 63) ? t0 : base + 63;
            int lo = (base > 1) ? base : 1;
            const unsigned char* rb = bpS[p];
            for (int t = hi; t >= lo; t--) {
                cur = rb[(t - base) * KK + cur];
                tagS[t - 1] = cur;
            }
        } else if (c > 0) {
            const uint4* src = (const uint4*)(g_bp + ((long)b * TT + (c - 1) * 64) * KK);
            uint4* dst = (uint4*)bpS[p ^ 1];
            for (int i = k - 1; i < 64 * KK / 16; i += 127) dst[i] = src[i];
        }
        __syncthreads();
    }

    // ---- decoded output + gold-path score + accuracy ----
    float sc = 0.f;
    int correct = 0;
    for (int t = k; t < TT; t += 128) {
        int tg = tagS[t];
        out[1 + b * TT + t] = (float)tg;
        int ref = __ldg(tag_ids + b * TT + t);
        if (t < len) {
            correct += (ref == tg);
            sc += __ldg(emissions + ((long)b * TT + t) * KK + ref);
            if (t >= 1) {
                int prev = __ldg(tag_ids + b * TT + t - 1);
                sc += __ldg(trans + prev * KK + ref);   // trans[prev][ref]
            }
        }
    }
    #pragma unroll
    for (int o = 16; o > 0; o >>= 1) {
        sc      += __shfl_xor_sync(0xffffffffu, sc, o);
        correct += __shfl_xor_sync(0xffffffffu, correct, o);
    }
    __syncthreads();
    if (lane == 0) { fredS[wid] = sc; iredS[wid] = correct; }
    __syncthreads();
    if (k == 0) {
        float S = fredS[0] + fredS[1] + fredS[2] + fredS[3];
        int   C = iredS[0] + iredS[1] + iredS[2] + iredS[3];
        g_ll[b]      = S - g_lognorm[b];
        g_correct[b] = C;
        g_total[b]   = len;
    }
}

// ============================================================
// Kernel 3: finalize loss + accuracy (deterministic).
// ============================================================
__global__ void crf_finalize_kernel(float* __restrict__ out)
{
    __shared__ float llS[BB];
    __shared__ int   cS[BB];
    __shared__ int   tS[BB];
    int k = threadIdx.x;   // 256 threads
    llS[k] = g_ll[k]; cS[k] = g_correct[k]; tS[k] = g_total[k];
    __syncthreads();
    if (k == 0) {
        float s = 0.f; int c = 0, t = 0;
        for (int i = 0; i < BB; i++) { s += llS[i]; c += cS[i]; t += tS[i]; }
        out[0] = -s / (float)BB;
        out[1 + BB * TT] = (float)c / (float)t;
    }
}

extern "C" void kernel_launch(void* const* d_in, const int* in_sizes, int n_in,
                              void* d_out, int out_size)
{
    const float* emissions = (const float*)d_in[0];   // (256,512,128) f32
    const int*   tag_ids   = (const int*)d_in[1];     // (256,512) i32
    const int*   lengths   = (const int*)d_in[2];     // (256,) i32
    const float* trans     = (const float*)d_in[3];   // (128,128) f32
    float* out = (float*)d_out;                       // [loss, decoded(B*T), acc]

    sort_kernel<<<1, BB>>>(lengths);
    crf_scan_kernel<<<2 * BB, 128>>>(emissions, lengths, trans);
    crf_backtrack_kernel<<<BB, 128>>>(emissions, tag_ids, lengths, trans, out);
    crf_finalize_kernel<<<1, BB>>>(out);
}

// round 10
// speedup vs baseline: 1.6228x; 1.6228x over previous
#include <cuda_runtime.h>

#define BB 256
#define TT 512
#define KK 128

// ---- scratch (no allocations allowed) ----
__device__ float g_v[(long)BB * TT * KK];   // 64MB: viterbi values per (b,t,k)
__device__ float g_transT[KK * KK];         // transT[c*K+j] = trans[j*K+c]
__device__ int   g_order[BB];               // batches sorted by length desc
__device__ float g_lognorm[BB];
__device__ float g_ll[BB];
__device__ int   g_correct[BB];
__device__ int   g_total[BB];

// ---- packed f32x2 helpers (sm_103a): add/fma only ----
__device__ __forceinline__ unsigned long long f2pack(float a, float b) {
    unsigned long long r;
    asm("mov.b64 %0, {%1,%2};" : "=l"(r) : "f"(a), "f"(b));
    return r;
}
__device__ __forceinline__ void f2unpack(unsigned long long v, float& a, float& b) {
    asm("mov.b64 {%0,%1}, %2;" : "=f"(a), "=f"(b) : "l"(v));
}
__device__ __forceinline__ unsigned long long f2add(unsigned long long a, unsigned long long b) {
    unsigned long long r;
    asm("add.rn.f32x2 %0, %1, %2;" : "=l"(r) : "l"(a), "l"(b));
    return r;
}
__device__ __forceinline__ unsigned long long f2fma(unsigned long long a, unsigned long long b,
                                                    unsigned long long c) {
    unsigned long long r;
    asm("fma.rn.f32x2 %0, %1, %2, %3;" : "=l"(r) : "l"(a), "l"(b), "l"(c));
    return r;
}

// ============================================================
// Kernel 0: prep = LPT sort (block 0) + transpose (blocks 1..128).
// ============================================================
__global__ __launch_bounds__(256)
void prep_kernel(const int* __restrict__ lengths, const float* __restrict__ trans)
{
    if (blockIdx.x == 0) {
        __shared__ int keys[BB];
        int b = threadIdx.x;
        int key = (lengths[b] << 8) | (BB - 1 - b);
        keys[b] = key;
        __syncthreads();
        int r = 0;
        #pragma unroll 8
        for (int j = 0; j < BB; j++) r += (keys[j] > key);
        g_order[r] = b;
    } else {
        int c = blockIdx.x - 1;
        int j = threadIdx.x;
        if (j < KK) g_transT[c * KK + j] = trans[j * KK + c];
    }
}

// ============================================================
// Kernel 1: fused scans with early exit at t = len.
// Blocks [0,256) = Viterbi forward (packed adds + scalar max,
// values only), blocks [256,512) = CRF forward (exp-domain).
// ============================================================
__global__ __launch_bounds__(128)
void crf_scan_kernel(const float* __restrict__ emissions,
                     const int*   __restrict__ lengths,
                     const float* __restrict__ trans)
{
    __shared__ ulonglong2 bufP[2][KK / 4];   // packed state vector (double buffer)
    __shared__ float      redS[2][4];

    const int k    = threadIdx.x;
    const int role = (blockIdx.x >= BB);
    const int b    = g_order[role ? (blockIdx.x - BB) : blockIdx.x];
    const int len  = lengths[b];
    const float* em = emissions + (long)b * TT * KK;
    const int wid = k >> 5, lane = k & 31;

    if (!role) {
        // -------- Viterbi forward: packed adds, scalar max, t < len --------
        unsigned long long trp[KK / 2];      // packed transition column k
        #pragma unroll
        for (int m = 0; m < KK / 2; m++)
            trp[m] = f2pack(trans[(2 * m) * KK + k], trans[(2 * m + 1) * KK + k]);

        float* vglob = g_v + (long)b * TT * KK;

        float v = em[k];                     // t = 0
        vglob[k] = v;
        int buf = 0;
        ((float*)bufP[0])[k] = v;
        __syncthreads();

        float emit = em[KK + k];             // prefetch t = 1
        for (int t = 1; t < len; t++) {
            float emit_next = (t + 1 < TT) ? em[(t + 1) * KK + k] : 0.0f;

            float b0 = -3.4e38f, b1 = -3.4e38f, b2 = -3.4e38f, b3 = -3.4e38f;
            #pragma unroll
            for (int jj = 0; jj < KK / 4; jj++) {
                ulonglong2 q = bufP[buf][jj];
                float x0, x1, x2, x3;
                f2unpack(f2add(q.x, trp[2 * jj]),     x0, x1);
                f2unpack(f2add(q.y, trp[2 * jj + 1]), x2, x3);
                b0 = fmaxf(b0, x0); b1 = fmaxf(b1, x1);
                b2 = fmaxf(b2, x2); b3 = fmaxf(b3, x3);
            }
            v = fmaxf(fmaxf(b0, b1), fmaxf(b2, b3)) + emit;
            vglob[t * KK + k] = v;

            ((float*)bufP[buf ^ 1])[k] = v;
            __syncthreads();
            buf ^= 1;
            emit = emit_next;
        }
    } else {
        // -------- CRF forward (log partition), exp-domain, t < len --------
        unsigned long long Ep[KK / 2];       // packed exp(transition) column k
        #pragma unroll
        for (int m = 0; m < KK / 2; m++)
            Ep[m] = f2pack(__expf(trans[(2 * m) * KK + k]),
                           __expf(trans[(2 * m + 1) * KK + k]));

        float alpha = em[k];
        int buf = 1;                         // first write goes to nb = 0

        float emit = em[KK + k];
        for (int t = 1; t < len; t++) {
            float emit_next = (t + 1 < TT) ? em[(t + 1) * KK + k] : 0.0f;

            // per-warp max of alpha
            float mw = alpha;
            #pragma unroll
            for (int o = 16; o > 0; o >>= 1)
                mw = fmaxf(mw, __shfl_xor_sync(0xffffffffu, mw, o));

            int nb = buf ^ 1;
            float p = __expf(alpha - mw);
            ((float*)bufP[nb])[k] = p;
            if (lane == 0) redS[nb][wid] = mw;
            __syncthreads();

            float m0 = redS[nb][0], m1 = redS[nb][1];
            float m2 = redS[nb][2], m3 = redS[nb][3];
            float m = fmaxf(fmaxf(m0, m1), fmaxf(m2, m3));

            // grouped packed dot: group g = warp g's p's (rescaled after)
            unsigned long long acc0 = f2pack(0.f, 0.f), acc1 = acc0,
                               acc2 = acc0, acc3 = acc0;
            #pragma unroll
            for (int jj = 0; jj < 8; jj++) {
                ulonglong2 q = bufP[nb][jj];
                acc0 = f2fma(q.x, Ep[2 * jj],     acc0);
                acc0 = f2fma(q.y, Ep[2 * jj + 1], acc0);
            }
            #pragma unroll
            for (int jj = 8; jj < 16; jj++) {
                ulonglong2 q = bufP[nb][jj];
                acc1 = f2fma(q.x, Ep[2 * jj],     acc1);
                acc1 = f2fma(q.y, Ep[2 * jj + 1], acc1);
            }
            #pragma unroll
            for (int jj = 16; jj < 24; jj++) {
                ulonglong2 q = bufP[nb][jj];
                acc2 = f2fma(q.x, Ep[2 * jj],     acc2);
                acc2 = f2fma(q.y, Ep[2 * jj + 1], acc2);
            }
            #pragma unroll
            for (int jj = 24; jj < 32; jj++) {
                ulonglong2 q = bufP[nb][jj];
                acc3 = f2fma(q.x, Ep[2 * jj],     acc3);
                acc3 = f2fma(q.y, Ep[2 * jj + 1], acc3);
            }
            float lo, hi, s;
            f2unpack(acc0, lo, hi); s = __expf(m0 - m) * (lo + hi);
            f2unpack(acc1, lo, hi); s = fmaf(__expf(m1 - m), lo + hi, s);
            f2unpack(acc2, lo, hi); s = fmaf(__expf(m2 - m), lo + hi, s);
            f2unpack(acc3, lo, hi); s = fmaf(__expf(m3 - m), lo + hi, s);

            alpha = m + __logf(s) + emit;
            buf = nb;
            emit = emit_next;
        }

        // final logsumexp over k
        __syncthreads();
        float mw = alpha;
        #pragma unroll
        for (int o = 16; o > 0; o >>= 1)
            mw = fmaxf(mw, __shfl_xor_sync(0xffffffffu, mw, o));
        if (lane == 0) redS[0][wid] = mw;
        __syncthreads();
        float m = fmaxf(fmaxf(redS[0][0], redS[0][1]), fmaxf(redS[0][2], redS[0][3]));
        float p = __expf(alpha - m);
        #pragma unroll
        for (int o = 16; o > 0; o >>= 1)
            p += __shfl_xor_sync(0xffffffffu, p, o);
        __syncthreads();
        if (lane == 0) redS[0][wid] = p;
        __syncthreads();
        if (k == 0) {
            float s = redS[0][0] + redS[0][1] + redS[0][2] + redS[0][3];
            g_lognorm[b] = m + __logf(s);
        }
    }
}

// ============================================================
// Kernel 2: backtrack by argmax recomputation along the path.
// 1 warp/batch. R5 argmax form (ballot+ffs+shfl) + two deltas:
// prefetch ring depth 4 (branch-free unroll) and transT L1 warm.
// ============================================================
__global__ __launch_bounds__(32)
void crf_backward_kernel(const float* __restrict__ emissions,
                         const int*   __restrict__ tag_ids,
                         const int*   __restrict__ lengths,
                         float*       __restrict__ out)
{
    __shared__ int tagS[TT];

    const int b    = blockIdx.x;
    const int lane = threadIdx.x;
    const int len  = lengths[b];
    const int t0   = len - 1;
    const float* vb = g_v + (long)b * TT * KK;

    // ---- warm transT into L1 (independent float4 loads, MLP) ----
    float wsum = 0.f;
    const float4* tT4 = (const float4*)g_transT;
    #pragma unroll 4
    for (int i = lane; i < KK * KK / 4; i += 32) {
        float4 w4 = __ldg(tT4 + i);
        wsum += w4.x + w4.y + w4.z + w4.w;
    }
    if (wsum == -1.2345e38f) tagS[0] = 7;   // keep loads alive; overwritten below

    // ---- last_tag = argmax(row len-1), first index on ties ----
    float4 q = __ldg((const float4*)(vb + (long)t0 * KK) + lane);
    float bv = q.x; int bi = 0;
    bool g1 = (q.y > bv); bi = g1 ? 1 : bi; bv = g1 ? q.y : bv;
    bool g2 = (q.z > bv); bi = g2 ? 2 : bi; bv = g2 ? q.z : bv;
    bool g3 = (q.w > bv); bi = g3 ? 3 : bi; bv = g3 ? q.w : bv;
    unsigned key = __float_as_uint(bv);
    key ^= ((unsigned)((int)key >> 31)) | 0x80000000u;   // ordered-uint map
    unsigned mk   = __reduce_max_sync(0xffffffffu, key);
    unsigned ball = __ballot_sync(0xffffffffu, key == mk);
    int src = __ffs(ball) - 1;
    int cur = (src << 2) + __shfl_sync(0xffffffffu, bi, src);

    // fill tail [t0, TT) with last_tag (matches identity backpointers)
    for (int t = t0 + lane; t < TT; t += 32) tagS[t] = cur;

    // ---- prefetch ring depth 4: ring[u] = row (t-1-u) ----
    float4 ring[4];
    #pragma unroll
    for (int u = 0; u < 4; u++) {
        int r = t0 - 1 - u; r = (r > 0) ? r : 0;
        ring[u] = __ldcs((const float4*)(vb + (long)r * KK) + lane);
    }

    int t = t0;
    while (t >= 5) {
        #pragma unroll
        for (int u = 0; u < 4; u++) {
            float4 vrow = ring[u];
            int nr = t - 5 - u; nr = (nr > 0) ? nr : 0;
            ring[u] = __ldcs((const float4*)(vb + (long)nr * KK) + lane);

            float4 tc4 = __ldg((const float4*)(g_transT + (cur << 7)) + lane);
            float w0 = vrow.x + tc4.x, w1 = vrow.y + tc4.y;
            float w2 = vrow.z + tc4.z, w3 = vrow.w + tc4.w;
            float lb = w0; int li = 0;
            bool h1 = (w1 > lb); li = h1 ? 1 : li; lb = h1 ? w1 : lb;
            bool h2 = (w2 > lb); li = h2 ? 2 : li; lb = h2 ? w2 : lb;
            bool h3 = (w3 > lb); li = h3 ? 3 : li; lb = h3 ? w3 : lb;
            unsigned k2 = __float_as_uint(lb);
            k2 ^= ((unsigned)((int)k2 >> 31)) | 0x80000000u;
            unsigned m2 = __reduce_max_sync(0xffffffffu, k2);
            unsigned b2 = __ballot_sync(0xffffffffu, k2 == m2);
            int s2 = __ffs(b2) - 1;
            cur = (s2 << 2) + __shfl_sync(0xffffffffu, li, s2);
            if (lane == 0) tagS[t - u - 1] = cur;
        }
        t -= 4;
    }
    for (; t >= 1; t--) {   // tail (<=4 steps, rows already fetched -> cache hits)
        float4 vrow = __ldcs((const float4*)(vb + (long)(t - 1) * KK) + lane);
        float4 tc4 = __ldg((const float4*)(g_transT + (cur << 7)) + lane);
        float w0 = vrow.x + tc4.x, w1 = vrow.y + tc4.y;
        float w2 = vrow.z + tc4.z, w3 = vrow.w + tc4.w;
        float lb = w0; int li = 0;
        bool h1 = (w1 > lb); li = h1 ? 1 : li; lb = h1 ? w1 : lb;
        bool h2 = (w2 > lb); li = h2 ? 2 : li; lb = h2 ? w2 : lb;
        bool h3 = (w3 > lb); li = h3 ? 3 : li; lb = h3 ? w3 : lb;
        unsigned k2 = __float_as_uint(lb);
        k2 ^= ((unsigned)((int)k2 >> 31)) | 0x80000000u;
        unsigned m2 = __reduce_max_sync(0xffffffffu, k2);
        unsigned b2 = __ballot_sync(0xffffffffu, k2 == m2);
        int s2 = __ffs(b2) - 1;
        cur = (s2 << 2) + __shfl_sync(0xffffffffu, li, s2);
        if (lane == 0) tagS[t - 1] = cur;
    }
    __syncwarp();

    // ---- decoded output + gold-path score + accuracy ----
    float sc = 0.f;
    int correct = 0;
    for (int tt = lane; tt < TT; tt += 32) {
        int tg = tagS[tt];
        out[1 + b * TT + tt] = (float)tg;
        int ref = __ldg(tag_ids + b * TT + tt);
        if (tt < len) {
            correct += (ref == tg);
            sc += __ldg(emissions + ((long)b * TT + tt) * KK + ref);
            if (tt >= 1) {
                int prev = __ldg(tag_ids + b * TT + tt - 1);
                sc += __ldg(g_transT + (ref << 7) + prev);   // trans[prev][ref]
            }
        }
    }
    #pragma unroll
    for (int o = 16; o > 0; o >>= 1) {
        sc      += __shfl_xor_sync(0xffffffffu, sc, o);
        correct += __shfl_xor_sync(0xffffffffu, correct, o);
    }
    if (lane == 0) {
        g_ll[b]      = sc - g_lognorm[b];
        g_correct[b] = correct;
        g_total[b]   = len;
    }
}

// ============================================================
// Kernel 3: finalize loss + accuracy (deterministic).
// ============================================================
__global__ void crf_finalize_kernel(float* __restrict__ out)
{
    __shared__ float llS[BB];
    __shared__ int   cS[BB];
    __shared__ int   tS[BB];
    int k = threadIdx.x;   // 256 threads
    llS[k] = g_ll[k]; cS[k] = g_correct[k]; tS[k] = g_total[k];
    __syncthreads();
    if (k == 0) {
        float s = 0.f; int c = 0, t = 0;
        for (int i = 0; i < BB; i++) { s += llS[i]; c += cS[i]; t += tS[i]; }
        out[0] = -s / (float)BB;
        out[1 + BB * TT] = (float)c / (float)t;
    }
}

extern "C" void kernel_launch(void* const* d_in, const int* in_sizes, int n_in,
                              void* d_out, int out_size)
{
    const float* emissions = (const float*)d_in[0];   // (256,512,128) f32
    const int*   tag_ids   = (const int*)d_in[1];     // (256,512) i32
    const int*   lengths   = (const int*)d_in[2];     // (256,) i32
    const float* trans     = (const float*)d_in[3];   // (128,128) f32
    float* out = (float*)d_out;                       // [loss, decoded(B*T), acc]

    prep_kernel<<<1 + KK, 256>>>(lengths, trans);
    crf_scan_kernel<<<2 * BB, 128>>>(emissions, lengths, trans);
    crf_backward_kernel<<<BB, 32>>>(emissions, tag_ids, lengths, out);
    crf_finalize_kernel<<<1, BB>>>(out);
}

// round 11
// speedup vs baseline: 1.7525x; 1.0799x over previous
#include <cuda_runtime.h>

#define BB 256
#define TT 512
#define KK 128

// ---- scratch (no allocations allowed) ----
__device__ float g_v[(long)BB * TT * KK];   // 64MB: viterbi values per (b,t,k)
__device__ float g_transT[KK * KK];         // transT[c*K+j] = trans[j*K+c]
__device__ int   g_order[BB];               // batches sorted by length desc
__device__ float g_lognorm[BB];
__device__ float g_gold[BB];                // gold-path score (lognorm subtracted later)
__device__ int   g_correct[BB];
__device__ int   g_total[BB];

// ---- packed f32x2 helpers (sm_103a): add/fma only ----
__device__ __forceinline__ unsigned long long f2pack(float a, float b) {
    unsigned long long r;
    asm("mov.b64 %0, {%1,%2};" : "=l"(r) : "f"(a), "f"(b));
    return r;
}
__device__ __forceinline__ void f2unpack(unsigned long long v, float& a, float& b) {
    asm("mov.b64 {%0,%1}, %2;" : "=f"(a), "=f"(b) : "l"(v));
}
__device__ __forceinline__ unsigned long long f2add(unsigned long long a, unsigned long long b) {
    unsigned long long r;
    asm("add.rn.f32x2 %0, %1, %2;" : "=l"(r) : "l"(a), "l"(b));
    return r;
}
__device__ __forceinline__ unsigned long long f2fma(unsigned long long a, unsigned long long b,
                                                    unsigned long long c) {
    unsigned long long r;
    asm("fma.rn.f32x2 %0, %1, %2, %3;" : "=l"(r) : "l"(a), "l"(b), "l"(c));
    return r;
}

// warp argmax over (packed 4-per-lane) candidates: returns global index 0..127.
// key must be the ordered-uint map of the lane-local best value; bi its sub-index.
__device__ __forceinline__ int warp_argmax_idx(unsigned key, int bi)
{
    unsigned mx = key;
    #pragma unroll
    for (int o = 16; o > 0; o >>= 1) {           // shfl butterfly max (no REDUX)
        unsigned ok = __shfl_xor_sync(0xffffffffu, mx, o);
        mx = (ok > mx) ? ok : mx;
    }
    unsigned ball = __ballot_sync(0xffffffffu, key == mx);
    int src = __ffs(ball) - 1;
    return (src << 2) + __shfl_sync(0xffffffffu, bi, src);
}

// ============================================================
// Kernel 0: prep = LPT sort (block 0) + transpose (blocks 1..128).
// ============================================================
__global__ __launch_bounds__(256)
void prep_kernel(const int* __restrict__ lengths, const float* __restrict__ trans)
{
    if (blockIdx.x == 0) {
        __shared__ int keys[BB];
        int b = threadIdx.x;
        int key = (lengths[b] << 8) | (BB - 1 - b);
        keys[b] = key;
        __syncthreads();
        int r = 0;
        #pragma unroll 8
        for (int j = 0; j < BB; j++) r += (keys[j] > key);
        g_order[r] = b;
    } else {
        int c = blockIdx.x - 1;
        int j = threadIdx.x;
        if (j < KK) g_transT[c * KK + j] = trans[j * KK + c];
    }
}

// ============================================================
// Kernel 1: fused scans + backtrack, early exit at t = len.
// Blocks [0,256): Viterbi forward (values) THEN warp-0 backtrack
// chase THEN block-wide epilogue (decoded/score/accuracy).
// Blocks [256,512): CRF forward (exp-domain logsumexp).
// ============================================================
__global__ __launch_bounds__(128)
void crf_scan_kernel(const float* __restrict__ emissions,
                     const int*   __restrict__ tag_ids,
                     const int*   __restrict__ lengths,
                     const float* __restrict__ trans,
                     float*       __restrict__ out)
{
    __shared__ ulonglong2 bufP[2][KK / 4];   // packed state vector (double buffer)
    __shared__ float      redS[2][4];
    __shared__ int        tagS[TT];
    __shared__ int        iredS[4];

    const int k    = threadIdx.x;
    const int role = (blockIdx.x >= BB);
    const int b    = g_order[role ? (blockIdx.x - BB) : blockIdx.x];
    const int len  = lengths[b];
    const float* em = emissions + (long)b * TT * KK;
    const int wid = k >> 5, lane = k & 31;

    if (!role) {
        // -------- Viterbi forward: packed adds, scalar max, t < len --------
        unsigned long long trp[KK / 2];      // packed transition column k
        #pragma unroll
        for (int m = 0; m < KK / 2; m++)
            trp[m] = f2pack(trans[(2 * m) * KK + k], trans[(2 * m + 1) * KK + k]);

        float* vglob = g_v + (long)b * TT * KK;

        float v = em[k];                     // t = 0
        vglob[k] = v;
        int buf = 0;
        ((float*)bufP[0])[k] = v;
        __syncthreads();

        float emit = em[KK + k];             // prefetch t = 1
        for (int t = 1; t < len; t++) {
            float emit_next = (t + 1 < TT) ? em[(t + 1) * KK + k] : 0.0f;

            float b0 = -3.4e38f, b1 = -3.4e38f, b2 = -3.4e38f, b3 = -3.4e38f;
            #pragma unroll
            for (int jj = 0; jj < KK / 4; jj++) {
                ulonglong2 q = bufP[buf][jj];
                float x0, x1, x2, x3;
                f2unpack(f2add(q.x, trp[2 * jj]),     x0, x1);
                f2unpack(f2add(q.y, trp[2 * jj + 1]), x2, x3);
                b0 = fmaxf(b0, x0); b1 = fmaxf(b1, x1);
                b2 = fmaxf(b2, x2); b3 = fmaxf(b3, x3);
            }
            v = fmaxf(fmaxf(b0, b1), fmaxf(b2, b3)) + emit;
            vglob[t * KK + k] = v;

            ((float*)bufP[buf ^ 1])[k] = v;
            __syncthreads();
            buf ^= 1;
            emit = emit_next;
        }

        // ==== backtrack chase: warp 0 only (others wait) ====
        if (wid == 0) {
            const int t0 = len - 1;
            const float* vb = vglob;

            // warm transT into L1 (independent float4 loads)
            float wsum = 0.f;
            const float4* tT4 = (const float4*)g_transT;
            #pragma unroll 4
            for (int i = lane; i < KK * KK / 4; i += 32) {
                float4 w4 = __ldg(tT4 + i);
                wsum += w4.x + w4.y + w4.z + w4.w;
            }

            // last_tag = argmax of final row (in smem bufP[buf])
            float4 q = ((const float4*)bufP[buf])[lane];
            float bv = q.x; int bi = 0;
            bool s1 = (q.y > bv); bi = s1 ? 1 : bi; bv = s1 ? q.y : bv;
            bool s2 = (q.z > bv); bi = s2 ? 2 : bi; bv = s2 ? q.z : bv;
            bool s3 = (q.w > bv); bi = s3 ? 3 : bi; bv = s3 ? q.w : bv;
            unsigned key = __float_as_uint(bv);
            key ^= ((unsigned)((int)key >> 31)) | 0x80000000u;
            if (wsum == -1.2345e38f) key = 0;        // keep warm loads alive
            int cur = warp_argmax_idx(key, bi);

            // tail fill [t0, TT)
            for (int t = t0 + lane; t < TT; t += 32) tagS[t] = cur;

            // prefetch ring depth 4: ring[u] = row (t-1-u)
            float4 ring[4];
            #pragma unroll
            for (int u = 0; u < 4; u++) {
                int r = t0 - 1 - u; r = (r > 0) ? r : 0;
                ring[u] = __ldcs((const float4*)(vb + (long)r * KK) + lane);
            }

            int t = t0;
            while (t >= 5) {
                #pragma unroll
                for (int u = 0; u < 4; u++) {
                    float4 vrow = ring[u];
                    int nr = t - 5 - u; nr = (nr > 0) ? nr : 0;
                    ring[u] = __ldcs((const float4*)(vb + (long)nr * KK) + lane);

                    float4 tc4 = __ldg((const float4*)(g_transT + (cur << 7)) + lane);
                    float w0 = vrow.x + tc4.x, w1 = vrow.y + tc4.y;
                    float w2 = vrow.z + tc4.z, w3 = vrow.w + tc4.w;
                    float lb = w0; int li = 0;
                    bool h1 = (w1 > lb); li = h1 ? 1 : li; lb = h1 ? w1 : lb;
                    bool h2 = (w2 > lb); li = h2 ? 2 : li; lb = h2 ? w2 : lb;
                    bool h3 = (w3 > lb); li = h3 ? 3 : li; lb = h3 ? w3 : lb;
                    unsigned k2 = __float_as_uint(lb);
                    k2 ^= ((unsigned)((int)k2 >> 31)) | 0x80000000u;
                    cur = warp_argmax_idx(k2, li);
                    if (lane == 0) tagS[t - u - 1] = cur;
                }
                t -= 4;
            }
            for (; t >= 1; t--) {
                float4 vrow = __ldcs((const float4*)(vb + (long)(t - 1) * KK) + lane);
                float4 tc4 = __ldg((const float4*)(g_transT + (cur << 7)) + lane);
                float w0 = vrow.x + tc4.x, w1 = vrow.y + tc4.y;
                float w2 = vrow.z + tc4.z, w3 = vrow.w + tc4.w;
                float lb = w0; int li = 0;
                bool h1 = (w1 > lb); li = h1 ? 1 : li; lb = h1 ? w1 : lb;
                bool h2 = (w2 > lb); li = h2 ? 2 : li; lb = h2 ? w2 : lb;
                bool h3 = (w3 > lb); li = h3 ? 3 : li; lb = h3 ? w3 : lb;
                unsigned k2 = __float_as_uint(lb);
                k2 ^= ((unsigned)((int)k2 >> 31)) | 0x80000000u;
                cur = warp_argmax_idx(k2, li);
                if (lane == 0) tagS[t - 1] = cur;
            }
        }
        __syncthreads();

        // ==== epilogue: decoded output + gold score + accuracy (128 thr) ====
        float sc = 0.f;
        int correct = 0;
        for (int t = k; t < TT; t += 128) {
            int tg = tagS[t];
            out[1 + b * TT + t] = (float)tg;
            int ref = __ldg(tag_ids + b * TT + t);
            if (t < len) {
                correct += (ref == tg);
                sc += __ldg(em + (long)t * KK + ref);
                if (t >= 1) {
                    int prev = __ldg(tag_ids + b * TT + t - 1);
                    sc += __ldg(g_transT + (ref << 7) + prev);   // trans[prev][ref]
                }
            }
        }
        #pragma unroll
        for (int o = 16; o > 0; o >>= 1) {
            sc      += __shfl_xor_sync(0xffffffffu, sc, o);
            correct += __shfl_xor_sync(0xffffffffu, correct, o);
        }
        if (lane == 0) { redS[0][wid] = sc; iredS[wid] = correct; }
        __syncthreads();
        if (k == 0) {
            float S = redS[0][0] + redS[0][1] + redS[0][2] + redS[0][3];
            int   C = iredS[0] + iredS[1] + iredS[2] + iredS[3];
            g_gold[b]    = S;
            g_correct[b] = C;
            g_total[b]   = len;
        }
    } else {
        // -------- CRF forward (log partition), exp-domain, t < len --------
        unsigned long long Ep[KK / 2];       // packed exp(transition) column k
        #pragma unroll
        for (int m = 0; m < KK / 2; m++)
            Ep[m] = f2pack(__expf(trans[(2 * m) * KK + k]),
                           __expf(trans[(2 * m + 1) * KK + k]));

        float alpha = em[k];
        int buf = 1;                         // first write goes to nb = 0

        float emit = em[KK + k];
        for (int t = 1; t < len; t++) {
            float emit_next = (t + 1 < TT) ? em[(t + 1) * KK + k] : 0.0f;

            float mw = alpha;
            #pragma unroll
            for (int o = 16; o > 0; o >>= 1)
                mw = fmaxf(mw, __shfl_xor_sync(0xffffffffu, mw, o));

            int nb = buf ^ 1;
            float p = __expf(alpha - mw);
            ((float*)bufP[nb])[k] = p;
            if (lane == 0) redS[nb][wid] = mw;
            __syncthreads();

            float m0 = redS[nb][0], m1 = redS[nb][1];
            float m2 = redS[nb][2], m3 = redS[nb][3];
            float m = fmaxf(fmaxf(m0, m1), fmaxf(m2, m3));

            unsigned long long acc0 = f2pack(0.f, 0.f), acc1 = acc0,
                               acc2 = acc0, acc3 = acc0;
            #pragma unroll
            for (int jj = 0; jj < 8; jj++) {
                ulonglong2 q = bufP[nb][jj];
                acc0 = f2fma(q.x, Ep[2 * jj],     acc0);
                acc0 = f2fma(q.y, Ep[2 * jj + 1], acc0);
            }
            #pragma unroll
            for (int jj = 8; jj < 16; jj++) {
                ulonglong2 q = bufP[nb][jj];
                acc1 = f2fma(q.x, Ep[2 * jj],     acc1);
                acc1 = f2fma(q.y, Ep[2 * jj + 1], acc1);
            }
            #pragma unroll
            for (int jj = 16; jj < 24; jj++) {
                ulonglong2 q = bufP[nb][jj];
                acc2 = f2fma(q.x, Ep[2 * jj],     acc2);
                acc2 = f2fma(q.y, Ep[2 * jj + 1], acc2);
            }
            #pragma unroll
            for (int jj = 24; jj < 32; jj++) {
                ulonglong2 q = bufP[nb][jj];
                acc3 = f2fma(q.x, Ep[2 * jj],     acc3);
                acc3 = f2fma(q.y, Ep[2 * jj + 1], acc3);
            }
            float lo, hi, s;
            f2unpack(acc0, lo, hi); s = __expf(m0 - m) * (lo + hi);
            f2unpack(acc1, lo, hi); s = fmaf(__expf(m1 - m), lo + hi, s);
            f2unpack(acc2, lo, hi); s = fmaf(__expf(m2 - m), lo + hi, s);
            f2unpack(acc3, lo, hi); s = fmaf(__expf(m3 - m), lo + hi, s);

            alpha = m + __logf(s) + emit;
            buf = nb;
            emit = emit_next;
        }

        // final logsumexp over k
        __syncthreads();
        float mw = alpha;
        #pragma unroll
        for (int o = 16; o > 0; o >>= 1)
            mw = fmaxf(mw, __shfl_xor_sync(0xffffffffu, mw, o));
        if (lane == 0) redS[0][wid] = mw;
        __syncthreads();
        float m = fmaxf(fmaxf(redS[0][0], redS[0][1]), fmaxf(redS[0][2], redS[0][3]));
        float p = __expf(alpha - m);
        #pragma unroll
        for (int o = 16; o > 0; o >>= 1)
            p += __shfl_xor_sync(0xffffffffu, p, o);
        __syncthreads();
        if (lane == 0) redS[0][wid] = p;
        __syncthreads();
        if (k == 0) {
            float s = redS[0][0] + redS[0][1] + redS[0][2] + redS[0][3];
            g_lognorm[b] = m + __logf(s);
        }
    }
}

// ============================================================
// Kernel 2: finalize loss + accuracy (deterministic).
// ============================================================
__global__ void crf_finalize_kernel(float* __restrict__ out)
{
    __shared__ float llS[BB];
    __shared__ int   cS[BB];
    __shared__ int   tS[BB];
    int k = threadIdx.x;   // 256 threads
    llS[k] = g_gold[k] - g_lognorm[k];
    cS[k] = g_correct[k]; tS[k] = g_total[k];
    __syncthreads();
    if (k == 0) {
        float s = 0.f; int c = 0, t = 0;
        for (int i = 0; i < BB; i++) { s += llS[i]; c += cS[i]; t += tS[i]; }
        out[0] = -s / (float)BB;
        out[1 + BB * TT] = (float)c / (float)t;
    }
}

extern "C" void kernel_launch(void* const* d_in, const int* in_sizes, int n_in,
                              void* d_out, int out_size)
{
    const float* emissions = (const float*)d_in[0];   // (256,512,128) f32
    const int*   tag_ids   = (const int*)d_in[1];     // (256,512) i32
    const int*   lengths   = (const int*)d_in[2];     // (256,) i32
    const float* trans     = (const float*)d_in[3];   // (128,128) f32
    float* out = (float*)d_out;                       // [loss, decoded(B*T), acc]

    prep_kernel<<<1 + KK, 256>>>(lengths, trans);
    crf_scan_kernel<<<2 * BB, 128>>>(emissions, tag_ids, lengths, trans, out);
    crf_finalize_kernel<<<1, BB>>>(out);
}